// round 10
// baseline (speedup 1.0000x reference)
#include <cuda_runtime.h>
#include <cstdint>

#define Bdim 32
#define Tdim 2048
#define Hdim 1024
#define Udim 1024
#define NCHUNK 16           // chunks per batch row
#define NWARP 4
#define THREADS 128
#define PBG 4               // batch rows per proj CTA

// Scratch (no allocs allowed)
__device__ float g_v[Bdim * Hdim];
__device__ float g_pm[Bdim * NCHUNK];
__device__ float g_pl[Bdim * NCHUNK];
__device__ float g_pctx[(size_t)Bdim * NCHUNK * Hdim];  // 2 MB
__device__ short g_list[Bdim][Tdim];                    // active t's per batch
__device__ int   g_cnt[Bdim];

__device__ __forceinline__ void cp16(uint32_t s, const float* g) {
    asm volatile("cp.async.cg.shared.global [%0], [%1], 16;" :: "r"(s), "l"(g));
}
#define CP_COMMIT() asm volatile("cp.async.commit_group;")
#define CP_WAIT0()  asm volatile("cp.async.wait_group 0;")
#define CP_WAIT1()  asm volatile("cp.async.wait_group 1;")
#define CP_WAIT2()  asm volatile("cp.async.wait_group 2;")

// ---------------------------------------------------------------------------
// Kernel 0: per-batch active-row compaction (order-free). Each CTA globally
// sniffs the mask storage format (whole 64KB-word view), then compacts its
// batch row's active timesteps into g_list[b] via smem atomic positions.
// ---------------------------------------------------------------------------
__global__ __launch_bounds__(256) void compact_kernel(const void* __restrict__ mraw) {
    const int b = blockIdx.x;
    __shared__ int s_ni, s_nf, s_cnt;
    if (threadIdx.x == 0) { s_ni = 0; s_nf = 0; s_cnt = 0; }
    __syncthreads();

    // global format sniff (safe: 16384 words == smallest possible buffer)
    const unsigned int* wv = (const unsigned int*)mraw;
    int bi = 0, bf = 0;
    #pragma unroll 4
    for (int i = threadIdx.x; i < (Bdim * Tdim) / 4; i += 256) {
        unsigned int x = wv[i];
        if (x > 1u) bi = 1;
        if (x != 0u && x != 0x3f800000u) bf = 1;
    }
    if (bi) atomicOr(&s_ni, 1);
    if (bf) atomicOr(&s_nf, 1);
    __syncthreads();
    const int mode = (!s_ni) ? 0 : ((!s_nf) ? 1 : 2);

    for (int t = threadIdx.x; t < Tdim; t += 256) {
        const int g = b * Tdim + t;
        bool act;
        if (mode == 0)      act = ((const int*)mraw)[g] != 0;
        else if (mode == 1) act = ((const float*)mraw)[g] != 0.f;
        else                act = ((const unsigned char*)mraw)[g] != 0;
        if (act) {
            int pos = atomicAdd(&s_cnt, 1);
            g_list[b][pos] = (short)t;
        }
    }
    __syncthreads();
    if (threadIdx.x == 0) g_cnt[b] = s_cnt;
}

// ---------------------------------------------------------------------------
// Kernel 1: v[b,h] = sum_u Wa[h,u]*dec[b,u].
// grid (Hdim/8, Bdim/PBG) = 1024 CTAs for DRAM-latency coverage of the 4MB
// Wa stream. Warp owns ONE h-row (32-reg Wa tile, front-batched MLP 8),
// dec tile (4 rows, 16 KB) in smem.
// ---------------------------------------------------------------------------
__global__ __launch_bounds__(256) void proj_kernel(const float* __restrict__ Wa,
                                                   const float* __restrict__ dec) {
    const int w    = threadIdx.x >> 5;
    const int lane = threadIdx.x & 31;
    const int b0   = blockIdx.y * PBG;
    const int h    = blockIdx.x * 8 + w;

    __shared__ __align__(16) float sdec[PBG][Udim];   // 16 KB

    {   // coalesced float4 load of the dec tile
        const float4* src = reinterpret_cast<const float4*>(dec + (size_t)b0 * Udim);
        float4* dst = reinterpret_cast<float4*>(&sdec[0][0]);
        #pragma unroll
        for (int i = 0; i < (PBG * Udim / 4) / 256; ++i)
            dst[i * 256 + threadIdx.x] = src[i * 256 + threadIdx.x];
    }
    __syncthreads();

    const float* wr = Wa + (size_t)h * Udim;
    float4 wv[8];
    #pragma unroll
    for (int k = 0; k < 8; ++k)
        wv[k] = *reinterpret_cast<const float4*>(wr + k * 128 + lane * 4);

    float acc[PBG];
    #pragma unroll
    for (int b = 0; b < PBG; ++b) acc[b] = 0.f;

    #pragma unroll
    for (int k = 0; k < 8; ++k) {
        #pragma unroll
        for (int b = 0; b < PBG; ++b) {
            float4 dd = *reinterpret_cast<const float4*>(&sdec[b][k * 128 + lane * 4]);
            acc[b] += wv[k].x * dd.x + wv[k].y * dd.y + wv[k].z * dd.z + wv[k].w * dd.w;
        }
    }
    #pragma unroll
    for (int b = 0; b < PBG; ++b) {
        float s = acc[b];
        #pragma unroll
        for (int o = 16; o; o >>= 1) s += __shfl_xor_sync(0xffffffffu, s, o);
        if (lane == 0) g_v[(b0 + b) * Hdim + h] = s;
    }
}

// ---------------------------------------------------------------------------
// Kernel 2: fused pass over a GLOBALLY balanced slice of the active-row list
// (CTA c of batch b gets [c*n/16, (c+1)*n/16) -> 64±1 rows for every CTA).
// v register-resident; rows staged via 3-stage cp.async ring, read once.
// ---------------------------------------------------------------------------
__global__ __launch_bounds__(THREADS, 4) void attn_main(const float* __restrict__ enc) {
    const int b    = blockIdx.y;
    const int c    = blockIdx.x;
    const int tid  = threadIdx.x;
    const int w    = tid >> 5;
    const int lane = tid & 31;

    __shared__ __align__(16) float sbuf[NWARP][3][Hdim];  // 48 KB ring buffers
    __shared__ float sm_[NWARP], sl_[NWARP];
    __shared__ short slist[Tdim / NCHUNK];                // <=128 rows per CTA

    // v slice register-resident
    float4 vv[8];
    {
        const float* vp = g_v + (size_t)b * Hdim;
        #pragma unroll
        for (int k = 0; k < 8; ++k)
            vv[k] = *reinterpret_cast<const float4*>(vp + k * 128 + lane * 4);
    }

    const int n     = g_cnt[b];
    const int start = (c * n) / NCHUNK;
    const int cnt   = ((c + 1) * n) / NCHUNK - start;
    for (int i = tid; i < cnt; i += THREADS) slist[i] = g_list[b][start + i];
    __syncthreads();

    const float* encb = enc + (size_t)b * Tdim * Hdim;
    const int nit = (cnt > w) ? (cnt - w + NWARP - 1) / NWARP : 0;

    float4 ctx[8];
    #pragma unroll
    for (int k = 0; k < 8; ++k) ctx[k] = make_float4(0.f, 0.f, 0.f, 0.f);
    float m = -1e30f, l = 0.f;

    uint32_t sb[3];
    #pragma unroll
    for (int s = 0; s < 3; ++s)
        sb[s] = (uint32_t)__cvta_generic_to_shared(&sbuf[w][s][0]);
    const uint32_t loff = lane * 16;

    int issued = 0;
    #pragma unroll
    for (int s = 0; s < 2; ++s) {
        if (issued < nit) {
            const float* gp = encb + (size_t)slist[w + NWARP * issued] * Hdim;
            #pragma unroll
            for (int k = 0; k < 8; ++k) cp16(sb[s] + k * 512 + loff, gp + k * 128 + lane * 4);
            CP_COMMIT();
            ++issued;
        }
    }

    for (int i = 0; i < nit; ++i) {
        if (issued < nit) {
            const uint32_t dst = sb[issued % 3];
            const float* gp = encb + (size_t)slist[w + NWARP * issued] * Hdim;
            #pragma unroll
            for (int k = 0; k < 8; ++k) cp16(dst + k * 512 + loff, gp + k * 128 + lane * 4);
            CP_COMMIT();
            ++issued;
        }
        const int pend = issued - i - 1;        // warp-uniform
        if (pend >= 2)      CP_WAIT2();
        else if (pend == 1) CP_WAIT1();
        else                CP_WAIT0();

        const float* bufc = &sbuf[w][i % 3][0];

        float4 cur[8];
        #pragma unroll
        for (int k = 0; k < 8; ++k)
            cur[k] = *reinterpret_cast<const float4*>(bufc + k * 128 + lane * 4);

        float s = 0.f;
        #pragma unroll
        for (int k = 0; k < 8; ++k)
            s += cur[k].x * vv[k].x + cur[k].y * vv[k].y
               + cur[k].z * vv[k].z + cur[k].w * vv[k].w;
        #pragma unroll
        for (int o = 16; o; o >>= 1) s += __shfl_xor_sync(0xffffffffu, s, o);

        float mnew = fmaxf(m, s);
        if (mnew != m) {
            float sc = __expf(m - mnew);   // first time: exp(-inf)=0, l/ctx are 0
            l *= sc;
            #pragma unroll
            for (int k = 0; k < 8; ++k) {
                ctx[k].x *= sc; ctx[k].y *= sc; ctx[k].z *= sc; ctx[k].w *= sc;
            }
            m = mnew;
        }
        float p = __expf(s - m);
        l += p;
        #pragma unroll
        for (int k = 0; k < 8; ++k) {
            ctx[k].x += p * cur[k].x; ctx[k].y += p * cur[k].y;
            ctx[k].z += p * cur[k].z; ctx[k].w += p * cur[k].w;
        }
    }

    // ---- merge 4 warps (reuse ring buffer 0 as per-warp ctx scratch) ----
    if (lane == 0) { sm_[w] = m; sl_[w] = l; }
    float* sctxw = &sbuf[w][0][0];
    #pragma unroll
    for (int k = 0; k < 8; ++k)
        *reinterpret_cast<float4*>(sctxw + k * 128 + lane * 4) = ctx[k];
    __syncthreads();

    float M = -1e30f;
    #pragma unroll
    for (int ww = 0; ww < NWARP; ++ww) M = fmaxf(M, sm_[ww]);
    float L = 0.f, wsc[NWARP];
    #pragma unroll
    for (int ww = 0; ww < NWARP; ++ww) {
        wsc[ww] = __expf(sm_[ww] - M);     // empty warp: exp(-1e30-M) -> 0
        L += sl_[ww] * wsc[ww];
    }

    const int idx = b * NCHUNK + c;
    #pragma unroll
    for (int half = 0; half < 2; ++half) {
        const int h4 = half * 512 + tid * 4;
        float4 acc = make_float4(0.f, 0.f, 0.f, 0.f);
        #pragma unroll
        for (int ww = 0; ww < NWARP; ++ww) {
            float4 pc = *reinterpret_cast<const float4*>(&sbuf[ww][0][h4]);
            acc.x += wsc[ww] * pc.x; acc.y += wsc[ww] * pc.y;
            acc.z += wsc[ww] * pc.z; acc.w += wsc[ww] * pc.w;
        }
        *reinterpret_cast<float4*>(&g_pctx[(size_t)idx * Hdim + h4]) = acc;
    }
    if (tid == 0) { g_pm[idx] = M; g_pl[idx] = L; }
}

// ---------------------------------------------------------------------------
// Kernel 3: merge NCHUNK=16 partials. grid (Bdim, 8) x 32 threads.
// ---------------------------------------------------------------------------
__global__ __launch_bounds__(32) void attn_reduce(float* __restrict__ out) {
    const int b    = blockIdx.x;
    const int lane = threadIdx.x;

    __shared__ float swgt[NCHUNK];
    __shared__ float sinv;

    float pm = (lane < NCHUNK) ? g_pm[b * NCHUNK + lane] : -1e30f;
    float pl = (lane < NCHUNK) ? g_pl[b * NCHUNK + lane] : 0.f;
    float M = pm;
    #pragma unroll
    for (int o = 16; o; o >>= 1) M = fmaxf(M, __shfl_xor_sync(0xffffffffu, M, o));
    float wg = __expf(pm - M);
    float Lc = wg * pl;
    #pragma unroll
    for (int o = 16; o; o >>= 1) Lc += __shfl_xor_sync(0xffffffffu, Lc, o);
    if (lane < NCHUNK) swgt[lane] = wg;
    if (lane == 0) sinv = (Lc > 0.f) ? 1.f / Lc : 0.f;   // all-masked row -> 0
    __syncwarp();

    const int h4 = blockIdx.y * 128 + lane * 4;
    const float* base = g_pctx + (size_t)b * NCHUNK * Hdim + h4;
    float4 acc = make_float4(0.f, 0.f, 0.f, 0.f);
    #pragma unroll
    for (int c = 0; c < NCHUNK; ++c) {
        float wgc = swgt[c];
        float4 p = *reinterpret_cast<const float4*>(base + (size_t)c * Hdim);
        acc.x += wgc * p.x; acc.y += wgc * p.y;
        acc.z += wgc * p.z; acc.w += wgc * p.w;
    }
    float inv = sinv;
    float4 o = make_float4(acc.x * inv, acc.y * inv, acc.z * inv, acc.w * inv);
    *reinterpret_cast<float4*>(&out[b * Hdim + h4]) = o;
}

// ---------------------------------------------------------------------------
extern "C" void kernel_launch(void* const* d_in, const int* in_sizes, int n_in,
                              void* d_out, int out_size) {
    const float* enc  = nullptr;   // 67108864
    const float* dec  = nullptr;   // 32768
    const void*  mask = nullptr;   // 65536
    const float* Wa   = nullptr;   // 1048576
    for (int i = 0; i < n_in; ++i) {
        switch (in_sizes[i]) {
            case 67108864: enc  = (const float*)d_in[i]; break;
            case 32768:    dec  = (const float*)d_in[i]; break;
            case 65536:    mask = d_in[i];               break;
            case 1048576:  Wa   = (const float*)d_in[i]; break;
        }
    }
    float* out = (float*)d_out;

    compact_kernel<<<Bdim, 256>>>(mask);
    proj_kernel<<<dim3(Hdim / 8, Bdim / PBG), 256>>>(Wa, dec);
    attn_main<<<dim3(NCHUNK, Bdim), THREADS>>>(enc);
    attn_reduce<<<dim3(Bdim, 8), 32>>>(out);
}

// round 11
// speedup vs baseline: 1.1593x; 1.1593x over previous
#include <cuda_runtime.h>
#include <cstdint>

#define Bdim 32
#define Tdim 2048
#define Hdim 1024
#define Udim 1024
#define NCHUNK 16           // chunks per batch row
#define CHUNK 128           // timesteps per CTA
#define NWARP 4
#define THREADS 128
#define PBG 4               // batch rows per proj CTA

// Scratch (no allocs allowed)
__device__ float g_v[Bdim * Hdim];
__device__ float g_pm[Bdim * NCHUNK];
__device__ float g_pl[Bdim * NCHUNK];
__device__ float g_pctx[(size_t)Bdim * NCHUNK * Hdim];  // 2 MB
__device__ int   g_mode;   // 0=int32 1=float32 2=uint8

__device__ __forceinline__ void cp16(uint32_t s, const float* g) {
    asm volatile("cp.async.cg.shared.global [%0], [%1], 16;" :: "r"(s), "l"(g));
}
#define CP_COMMIT() asm volatile("cp.async.commit_group;")
#define CP_WAIT0()  asm volatile("cp.async.wait_group 0;")
#define CP_WAIT1()  asm volatile("cp.async.wait_group 1;")
#define CP_WAIT2()  asm volatile("cp.async.wait_group 2;")

// ---------------------------------------------------------------------------
// Kernel 1: v[b,h] = sum_u Wa[h,u]*dec[b,u].
// grid (Hdim/8, Bdim/PBG) = 1024 CTAs (occupancy for the 4MB Wa DRAM stream).
// Warp owns ONE h-row: 32-reg Wa tile front-batched (MLP 8), dec tile (4 rows,
// 16 KB) in smem. Block (0,0) also sniffs the mask storage format.
// ---------------------------------------------------------------------------
__global__ __launch_bounds__(256) void proj_kernel(const float* __restrict__ Wa,
                                                   const float* __restrict__ dec,
                                                   const unsigned int* __restrict__ mw) {
    const int w    = threadIdx.x >> 5;
    const int lane = threadIdx.x & 31;
    const int b0   = blockIdx.y * PBG;
    const int h    = blockIdx.x * 8 + w;

    __shared__ __align__(16) float sdec[PBG][Udim];   // 16 KB
    __shared__ int s_ni, s_nf;
    if (threadIdx.x == 0) { s_ni = 0; s_nf = 0; }

    {   // coalesced float4 load of the dec tile
        const float4* src = reinterpret_cast<const float4*>(dec + (size_t)b0 * Udim);
        float4* dst = reinterpret_cast<float4*>(&sdec[0][0]);
        #pragma unroll
        for (int i = 0; i < (PBG * Udim / 4) / 256; ++i)
            dst[i * 256 + threadIdx.x] = src[i * 256 + threadIdx.x];
    }
    __syncthreads();

    const float* wr = Wa + (size_t)h * Udim;
    float4 wv[8];
    #pragma unroll
    for (int k = 0; k < 8; ++k)
        wv[k] = *reinterpret_cast<const float4*>(wr + k * 128 + lane * 4);

    float acc[PBG];
    #pragma unroll
    for (int b = 0; b < PBG; ++b) acc[b] = 0.f;

    #pragma unroll
    for (int k = 0; k < 8; ++k) {
        #pragma unroll
        for (int b = 0; b < PBG; ++b) {
            float4 dd = *reinterpret_cast<const float4*>(&sdec[b][k * 128 + lane * 4]);
            acc[b] += wv[k].x * dd.x + wv[k].y * dd.y + wv[k].z * dd.z + wv[k].w * dd.w;
        }
    }
    #pragma unroll
    for (int b = 0; b < PBG; ++b) {
        float s = acc[b];
        #pragma unroll
        for (int o = 16; o; o >>= 1) s += __shfl_xor_sync(0xffffffffu, s, o);
        if (lane == 0) g_v[(b0 + b) * Hdim + h] = s;
    }

    if (blockIdx.x == 0 && blockIdx.y == 0) {   // mask format sniff
        int bi = 0, bf = 0;
        for (int i = threadIdx.x; i < (Bdim * Tdim) / 4; i += 256) {
            unsigned int x = mw[i];
            if (x > 1u) bi = 1;
            if (x != 0u && x != 0x3f800000u) bf = 1;
        }
        if (bi) atomicOr(&s_ni, 1);
        if (bf) atomicOr(&s_nf, 1);
        __syncthreads();
        if (threadIdx.x == 0)
            g_mode = (!s_ni) ? 0 : ((!s_nf) ? 1 : 2);
    }
}

// ---------------------------------------------------------------------------
// Kernel 2 (identical to the 41.7us version): fused pass, v register-resident,
// per-CTA ORDERED row compaction over a CONTIGUOUS 128-row chunk (streaming
// DRAM locality preserved), 3-stage cp.async ring, rows read into regs once.
// ---------------------------------------------------------------------------
__global__ __launch_bounds__(THREADS, 4) void attn_main(const float* __restrict__ enc,
                                                        const void* __restrict__ mraw) {
    const int b    = blockIdx.y;
    const int c    = blockIdx.x;
    const int tid  = threadIdx.x;
    const int w    = tid >> 5;
    const int lane = tid & 31;

    __shared__ __align__(16) float sbuf[NWARP][3][Hdim];  // 48 KB ring buffers
    __shared__ float sm_[NWARP], sl_[NWARP];
    __shared__ unsigned sflags[NWARP];
    __shared__ short slist[CHUNK];

    // v slice register-resident (same 4KB read by all 4 warps; L2-served)
    float4 vv[8];
    {
        const float* vp = g_v + (size_t)b * Hdim;
        #pragma unroll
        for (int k = 0; k < 8; ++k)
            vv[k] = *reinterpret_cast<const float4*>(vp + k * 128 + lane * 4);
    }

    // ---- build compacted active-row list (tid == row-in-chunk, CHUNK==128) --
    const int mode  = g_mode;
    const int tglob = b * Tdim + c * CHUNK + tid;
    bool act;
    if (mode == 0)      act = ((const int*)mraw)[tglob] != 0;
    else if (mode == 1) act = ((const float*)mraw)[tglob] != 0.f;
    else                act = ((const unsigned char*)mraw)[tglob] != 0;
    unsigned bal = __ballot_sync(0xffffffffu, act);
    if (lane == 0) sflags[w] = bal;
    __syncthreads();

    int count = 0;
    #pragma unroll
    for (int g = 0; g < NWARP; ++g) count += __popc(sflags[g]);
    if (act) {
        int pre = 0;
        #pragma unroll
        for (int g = 0; g < NWARP; ++g) if (g < w) pre += __popc(sflags[g]);
        pre += __popc(bal & ((1u << lane) - 1u));
        slist[pre] = (short)tid;
    }
    __syncthreads();

    const float* rowp = enc + (size_t)b * Tdim * Hdim + (size_t)c * CHUNK * Hdim;
    const int nit = (count > w) ? (count - w + NWARP - 1) / NWARP : 0;

    float4 ctx[8];
    #pragma unroll
    for (int k = 0; k < 8; ++k) ctx[k] = make_float4(0.f, 0.f, 0.f, 0.f);
    float m = -1e30f, l = 0.f;

    uint32_t sb[3];
    #pragma unroll
    for (int s = 0; s < 3; ++s)
        sb[s] = (uint32_t)__cvta_generic_to_shared(&sbuf[w][s][0]);
    const uint32_t loff = lane * 16;

    int issued = 0;
    #pragma unroll
    for (int s = 0; s < 2; ++s) {
        if (issued < nit) {
            const float* gp = rowp + (size_t)slist[w + NWARP * issued] * Hdim;
            #pragma unroll
            for (int k = 0; k < 8; ++k) cp16(sb[s] + k * 512 + loff, gp + k * 128 + lane * 4);
            CP_COMMIT();
            ++issued;
        }
    }

    for (int i = 0; i < nit; ++i) {
        if (issued < nit) {
            const uint32_t dst = sb[issued % 3];
            const float* gp = rowp + (size_t)slist[w + NWARP * issued] * Hdim;
            #pragma unroll
            for (int k = 0; k < 8; ++k) cp16(dst + k * 512 + loff, gp + k * 128 + lane * 4);
            CP_COMMIT();
            ++issued;
        }
        const int pend = issued - i - 1;        // warp-uniform
        if (pend >= 2)      CP_WAIT2();
        else if (pend == 1) CP_WAIT1();
        else                CP_WAIT0();

        const float* bufc = &sbuf[w][i % 3][0];

        float4 cur[8];
        #pragma unroll
        for (int k = 0; k < 8; ++k)
            cur[k] = *reinterpret_cast<const float4*>(bufc + k * 128 + lane * 4);

        float s = 0.f;
        #pragma unroll
        for (int k = 0; k < 8; ++k)
            s += cur[k].x * vv[k].x + cur[k].y * vv[k].y
               + cur[k].z * vv[k].z + cur[k].w * vv[k].w;
        #pragma unroll
        for (int o = 16; o; o >>= 1) s += __shfl_xor_sync(0xffffffffu, s, o);

        float mnew = fmaxf(m, s);
        if (mnew != m) {
            float sc = __expf(m - mnew);   // first time: exp(-inf)=0, l/ctx are 0
            l *= sc;
            #pragma unroll
            for (int k = 0; k < 8; ++k) {
                ctx[k].x *= sc; ctx[k].y *= sc; ctx[k].z *= sc; ctx[k].w *= sc;
            }
            m = mnew;
        }
        float p = __expf(s - m);
        l += p;
        #pragma unroll
        for (int k = 0; k < 8; ++k) {
            ctx[k].x += p * cur[k].x; ctx[k].y += p * cur[k].y;
            ctx[k].z += p * cur[k].z; ctx[k].w += p * cur[k].w;
        }
    }

    // ---- merge 4 warps (reuse ring buffer 0 as per-warp ctx scratch) ----
    if (lane == 0) { sm_[w] = m; sl_[w] = l; }
    float* sctxw = &sbuf[w][0][0];
    #pragma unroll
    for (int k = 0; k < 8; ++k)
        *reinterpret_cast<float4*>(sctxw + k * 128 + lane * 4) = ctx[k];
    __syncthreads();

    float M = -1e30f;
    #pragma unroll
    for (int ww = 0; ww < NWARP; ++ww) M = fmaxf(M, sm_[ww]);
    float L = 0.f, wsc[NWARP];
    #pragma unroll
    for (int ww = 0; ww < NWARP; ++ww) {
        wsc[ww] = __expf(sm_[ww] - M);     // empty warp: exp(-1e30-M) -> 0
        L += sl_[ww] * wsc[ww];
    }

    const int idx = b * NCHUNK + c;
    #pragma unroll
    for (int half = 0; half < 2; ++half) {
        const int h4 = half * 512 + tid * 4;
        float4 acc = make_float4(0.f, 0.f, 0.f, 0.f);
        #pragma unroll
        for (int ww = 0; ww < NWARP; ++ww) {
            float4 pc = *reinterpret_cast<const float4*>(&sbuf[ww][0][h4]);
            acc.x += wsc[ww] * pc.x; acc.y += wsc[ww] * pc.y;
            acc.z += wsc[ww] * pc.z; acc.w += wsc[ww] * pc.w;
        }
        *reinterpret_cast<float4*>(&g_pctx[(size_t)idx * Hdim + h4]) = acc;
    }
    if (tid == 0) { g_pm[idx] = M; g_pl[idx] = L; }
}

// ---------------------------------------------------------------------------
// Kernel 3: merge partials — re-parallelized. grid (Bdim, 8) x 256 threads:
// block owns 32 float4 columns; thread group g (of 8) loads only chunks
// {2g, 2g+1}; smem tree combines the 8 groups. 2048 warps chip-wide.
// ---------------------------------------------------------------------------
__global__ __launch_bounds__(256) void attn_reduce(float* __restrict__ out) {
    const int b   = blockIdx.x;
    const int tid = threadIdx.x;

    __shared__ float swgt[NCHUNK];
    __shared__ float sinv;
    __shared__ __align__(16) float4 sred[8][32];

    if (tid < 32) {
        float pm = (tid < NCHUNK) ? g_pm[b * NCHUNK + tid] : -1e30f;
        float pl = (tid < NCHUNK) ? g_pl[b * NCHUNK + tid] : 0.f;
        float M = pm;
        #pragma unroll
        for (int o = 16; o; o >>= 1) M = fmaxf(M, __shfl_xor_sync(0xffffffffu, M, o));
        float wg = __expf(pm - M);
        float Lc = wg * pl;
        #pragma unroll
        for (int o = 16; o; o >>= 1) Lc += __shfl_xor_sync(0xffffffffu, Lc, o);
        if (tid < NCHUNK) swgt[tid] = wg;
        if (tid == 0) sinv = (Lc > 0.f) ? 1.f / Lc : 0.f;   // all-masked row -> 0
    }
    __syncthreads();

    const int col = tid & 31;          // float4 column within block's 32
    const int grp = tid >> 5;          // 0..7 -> chunks {2g, 2g+1}
    const int h4  = (blockIdx.y * 32 + col) * 4;
    const float* base = g_pctx + (size_t)b * NCHUNK * Hdim + h4;

    float4 acc = make_float4(0.f, 0.f, 0.f, 0.f);
    #pragma unroll
    for (int q = 0; q < 2; ++q) {
        const int cc = grp * 2 + q;
        float wg = swgt[cc];
        float4 p = *reinterpret_cast<const float4*>(base + (size_t)cc * Hdim);
        acc.x += wg * p.x; acc.y += wg * p.y; acc.z += wg * p.z; acc.w += wg * p.w;
    }
    sred[grp][col] = acc;
    __syncthreads();

    if (grp == 0) {
        #pragma unroll
        for (int g = 1; g < 8; ++g) {
            float4 p = sred[g][col];
            acc.x += p.x; acc.y += p.y; acc.z += p.z; acc.w += p.w;
        }
        float inv = sinv;
        float4 o = make_float4(acc.x * inv, acc.y * inv, acc.z * inv, acc.w * inv);
        *reinterpret_cast<float4*>(&out[b * Hdim + h4]) = o;
    }
}

// ---------------------------------------------------------------------------
extern "C" void kernel_launch(void* const* d_in, const int* in_sizes, int n_in,
                              void* d_out, int out_size) {
    const float* enc  = nullptr;   // 67108864
    const float* dec  = nullptr;   // 32768
    const void*  mask = nullptr;   // 65536
    const float* Wa   = nullptr;   // 1048576
    for (int i = 0; i < n_in; ++i) {
        switch (in_sizes[i]) {
            case 67108864: enc  = (const float*)d_in[i]; break;
            case 32768:    dec  = (const float*)d_in[i]; break;
            case 65536:    mask = d_in[i];               break;
            case 1048576:  Wa   = (const float*)d_in[i]; break;
        }
    }
    float* out = (float*)d_out;

    proj_kernel<<<dim3(Hdim / 8, Bdim / PBG), 256>>>(Wa, dec, (const unsigned int*)mask);
    attn_main<<<dim3(NCHUNK, Bdim), THREADS>>>(enc, mask);
    attn_reduce<<<dim3(Bdim, 8), 256>>>(out);
}